// round 2
// baseline (speedup 1.0000x reference)
#include <cuda_runtime.h>
#include <math.h>

// ---------------------------------------------------------------------------
// StableResonatorBank: B=8, S=4096, D=1024, R=256
//   resonance[b,s,r] = (x[b,s,:]/||x||) . (freq[r,:]/||freq||)
//   xm = mean_s x; gate = hard(sigmoid(xm@gate_w^T + gate_bias), 0.001)
//   retention = sigmoid(xm@ret_w^T + ret_bias)
//   signal = resonance * gate;  scan: acc_t = sig_t + acc_{t-1}*retention
//   output = acc @ out_w^T ; final_state = acc_{S-1}
// ---------------------------------------------------------------------------

#define BB 8
#define SS 4096
#define DD 1024
#define RR 256
#define SEGS 16

typedef unsigned long long u64;

// Scratch (static device memory; no allocation anywhere)
__device__ float g_invnf[RR];
__device__ float g_invnx[BB * SS];
__device__ float g_xm_part[BB * SEGS * DD];
__device__ float g_xm[BB * DD];
__device__ float g_gate[BB * RR];
__device__ float g_ret[BB * RR];
__device__ float g_signal[BB * SS * RR];  // 33.5 MB
__device__ float g_acc[BB * SS * RR];     // 33.5 MB

// ---------------- packed f32x2 helpers -------------------------------------
__device__ __forceinline__ u64 pack2(float lo, float hi) {
    u64 r;
    asm("mov.b64 %0, {%1, %2};" : "=l"(r) : "f"(lo), "f"(hi));
    return r;
}
__device__ __forceinline__ void fma2(u64& d, u64 a, u64 b) {
    asm("fma.rn.f32x2 %0, %1, %2, %0;" : "+l"(d) : "l"(a), "l"(b));
}
__device__ __forceinline__ void unpack2(u64 v, float& lo, float& hi) {
    asm("mov.b64 {%0, %1}, %2;" : "=f"(lo), "=f"(hi) : "l"(v));
}

// ---------------- row inverse L2 norms (rows of length 1024) ---------------
// WHICH = 0 -> g_invnf, 1 -> g_invnx
template <int WHICH>
__global__ void rownorm_kernel(const float* __restrict__ src, int rows) {
    int warp = (blockIdx.x * blockDim.x + threadIdx.x) >> 5;
    int lane = threadIdx.x & 31;
    if (warp >= rows) return;
    const float4* p = (const float4*)(src + (size_t)warp * DD);
    float ss = 0.f;
#pragma unroll
    for (int i = 0; i < 8; i++) {
        float4 v = p[lane + 32 * i];
        ss += v.x * v.x + v.y * v.y + v.z * v.z + v.w * v.w;
    }
#pragma unroll
    for (int o = 16; o > 0; o >>= 1) ss += __shfl_xor_sync(0xFFFFFFFFu, ss, o);
    if (lane == 0) {
        float inv = 1.0f / fmaxf(sqrtf(ss), 1e-12f);
        if (WHICH == 0) g_invnf[warp] = inv; else g_invnx[warp] = inv;
    }
}

// ---------------- column means of x (two-phase, deterministic) -------------
__global__ void mean_partial_kernel(const float* __restrict__ x) {
    int d = blockIdx.x * 256 + threadIdx.x;           // 0..1023 (grid.x = 4)
    int seg = blockIdx.y;                             // 0..15
    int b = blockIdx.z;                               // 0..7
    const int L = SS / SEGS;                          // 256
    const float* p = x + ((size_t)b * SS + (size_t)seg * L) * DD + d;
    float s = 0.f;
#pragma unroll 4
    for (int t = 0; t < L; t++) s += p[(size_t)t * DD];
    g_xm_part[(b * SEGS + seg) * DD + d] = s;
}

__global__ void mean_reduce_kernel() {
    int i = blockIdx.x * 256 + threadIdx.x;           // b*DD + d (8192)
    float s = 0.f;
#pragma unroll
    for (int seg = 0; seg < SEGS; seg++)
        s += g_xm_part[((i >> 10) * SEGS + seg) * DD + (i & (DD - 1))];
    g_xm[i] = s * (1.0f / (float)SS);
}

// ---------------- gate / retention (one warp per (b,r)) --------------------
__global__ void gate_ret_kernel(const float* __restrict__ gate_w,
                                const float* __restrict__ gate_bias,
                                const float* __restrict__ ret_w,
                                const float* __restrict__ ret_bias) {
    int warp = (blockIdx.x * blockDim.x + threadIdx.x) >> 5;  // 0..2047
    int lane = threadIdx.x & 31;
    if (warp >= BB * RR) return;
    int b = warp >> 8, r = warp & (RR - 1);
    const float* xm = g_xm + (size_t)b * DD;
    const float* gw = gate_w + (size_t)r * DD;
    const float* rw = ret_w + (size_t)r * DD;
    float s1 = 0.f, s2 = 0.f;
#pragma unroll 8
    for (int i = lane; i < DD; i += 32) {
        float xv = xm[i];
        s1 = fmaf(xv, gw[i], s1);
        s2 = fmaf(xv, rw[i], s2);
    }
#pragma unroll
    for (int o = 16; o > 0; o >>= 1) {
        s1 += __shfl_xor_sync(0xFFFFFFFFu, s1, o);
        s2 += __shfl_xor_sync(0xFFFFFFFFu, s2, o);
    }
    if (lane == 0) {
        float gs = 1.0f / (1.0f + expf(-(s1 + gate_bias[r])));
        g_gate[warp] = (gs >= 0.001f) ? gs : 0.0f;   // straight-through hard gate (fwd)
        g_ret[warp] = 1.0f / (1.0f + expf(-(s2 + ret_bias[r])));
    }
}

// ---------------- f32x2 SGEMM: C[M,N] = A[M,K] * B[N,K]^T ------------------
// 128x128 tile, BK=8, 256 threads, TM=TN=8 per thread, FFMA2 inner loop.
// MODE 1: A = x (param), C = g_signal, epilogue scales by invnx*invnf*gate.
// MODE 2: A = g_acc (global), C = out (param), plain write.
template <int MODE>
__global__ __launch_bounds__(256) void sgemm_f32x2_kernel(
    const float* __restrict__ Ain, const float* __restrict__ Bm,
    float* __restrict__ Cout, int M, int N, int K) {
    const int BM = 128, BN = 128, BK = 8, TM = 8, TN = 8;
    __shared__ float As[2][BK][BM];
    __shared__ u64 Bs2[2][BK][BN];   // B values pre-duplicated: Bs2[..][n] = (b,b)

    const float* A = (MODE == 1) ? Ain : g_acc;
    int tid = threadIdx.x;
    int bm = blockIdx.x, bn = blockIdx.y;
    int lr = tid >> 1;            // 0..127: tile row for loading
    int lc = (tid & 1) << 2;      // 0 or 4: k offset (float4)
    int tx = tid & 15;            // n-direction thread
    int ty = tid >> 4;            // m-direction thread
    const float* Ap = A + (size_t)(bm * BM + lr) * K + lc;
    const float* Bp = Bm + (size_t)(bn * BN + lr) * K + lc;

    u64 acc2[4][TN];              // acc2[i2][j] = (C[2*i2][j], C[2*i2+1][j])
#pragma unroll
    for (int i = 0; i < 4; i++)
#pragma unroll
        for (int j = 0; j < TN; j++) acc2[i][j] = 0ULL;

    // stage tile 0
    {
        float4 av = *(const float4*)Ap;
        float4 bv = *(const float4*)Bp;
        As[0][lc + 0][lr] = av.x; As[0][lc + 1][lr] = av.y;
        As[0][lc + 2][lr] = av.z; As[0][lc + 3][lr] = av.w;
        Bs2[0][lc + 0][lr] = pack2(bv.x, bv.x);
        Bs2[0][lc + 1][lr] = pack2(bv.y, bv.y);
        Bs2[0][lc + 2][lr] = pack2(bv.z, bv.z);
        Bs2[0][lc + 3][lr] = pack2(bv.w, bv.w);
    }
    __syncthreads();

    const int NT = K / BK;
    for (int t = 0; t < NT; t++) {
        float4 av, bv;
        if (t + 1 < NT) {                 // prefetch next tile (hidden by compute)
            av = *(const float4*)(Ap + (t + 1) * BK);
            bv = *(const float4*)(Bp + (t + 1) * BK);
        }
        int buf = t & 1;
#pragma unroll
        for (int k = 0; k < BK; k++) {
            const u64* arow = (const u64*)(&As[buf][k][ty * TM]);  // 4 m-pairs
            const u64* brow = &Bs2[buf][k][tx * TN];               // 8 dup pairs
            u64 b2[TN];
#pragma unroll
            for (int j = 0; j < TN; j++) b2[j] = brow[j];
#pragma unroll
            for (int i = 0; i < 4; i++) {
                u64 a2 = arow[i];
#pragma unroll
                for (int j = 0; j < TN; j++) fma2(acc2[i][j], a2, b2[j]);
            }
        }
        if (t + 1 < NT) {
            int nb = (t + 1) & 1;
            As[nb][lc + 0][lr] = av.x; As[nb][lc + 1][lr] = av.y;
            As[nb][lc + 2][lr] = av.z; As[nb][lc + 3][lr] = av.w;
            Bs2[nb][lc + 0][lr] = pack2(bv.x, bv.x);
            Bs2[nb][lc + 1][lr] = pack2(bv.y, bv.y);
            Bs2[nb][lc + 2][lr] = pack2(bv.z, bv.z);
            Bs2[nb][lc + 3][lr] = pack2(bv.w, bv.w);
        }
        __syncthreads();
    }

    float* C = (MODE == 1) ? g_signal : Cout;
    int bb = (bm * BM) / SS;   // batch of this row tile (SS % BM == 0)
#pragma unroll
    for (int i = 0; i < TM; i++) {
        int grow = bm * BM + ty * TM + i;
        float rs = (MODE == 1) ? g_invnx[grow] : 1.0f;
        float o[TN];
#pragma unroll
        for (int j = 0; j < TN; j++) {
            float lo, hi;
            unpack2(acc2[i >> 1][j], lo, hi);
            float v = (i & 1) ? hi : lo;
            if (MODE == 1) {
                int gcol = bn * BN + tx * TN + j;
                v *= rs * g_invnf[gcol] * g_gate[bb * RR + gcol];
            }
            o[j] = v;
        }
        float4* cp = (float4*)(C + (size_t)grow * N + bn * BN + tx * TN);
        cp[0] = make_float4(o[0], o[1], o[2], o[3]);
        cp[1] = make_float4(o[4], o[5], o[6], o[7]);
    }
}

// ---------------- scan: acc_t = sig_t + acc_{t-1} * retention --------------
__global__ void scan_kernel(const float* __restrict__ prev_state,
                            float* __restrict__ final_state_out) {
    int c = blockIdx.x * blockDim.x + threadIdx.x;  // chain id 0..2047
    if (c >= BB * RR) return;
    int b = c >> 8, r = c & (RR - 1);
    float st = prev_state[c];
    float ret = g_ret[c];
    size_t base = (size_t)b * SS * RR + r;
#pragma unroll 8
    for (int t = 0; t < SS; t++) {
        float v = g_signal[base + (size_t)t * RR];
        st = fmaf(st, ret, v);
        g_acc[base + (size_t)t * RR] = st;
    }
    if (final_state_out) final_state_out[c] = st;
}

// ---------------------------------------------------------------------------
extern "C" void kernel_launch(void* const* d_in, const int* in_sizes, int n_in,
                              void* d_out, int out_size) {
    const float* x         = (const float*)d_in[0];
    const float* prev_st   = (const float*)d_in[1];
    const float* freq      = (const float*)d_in[2];
    const float* ret_bias  = (const float*)d_in[3];
    const float* ret_w     = (const float*)d_in[4];
    const float* gate_w    = (const float*)d_in[5];
    const float* gate_bias = (const float*)d_in[6];
    const float* out_w     = (const float*)d_in[7];
    float* out = (float*)d_out;

    const int M = BB * SS;  // 32768

    // 1) inverse norms
    rownorm_kernel<0><<<RR / 8, 256>>>(freq, RR);
    rownorm_kernel<1><<<M / 8, 256>>>(x, M);

    // 2) column means of x
    mean_partial_kernel<<<dim3(DD / 256, SEGS, BB), 256>>>(x);
    mean_reduce_kernel<<<(BB * DD) / 256, 256>>>();

    // 3) gate + retention
    gate_ret_kernel<<<(BB * RR) / 8, 256>>>(gate_w, gate_bias, ret_w, ret_bias);

    // 4) GEMM1 + fused normalization + gate -> g_signal (M x R)
    sgemm_f32x2_kernel<1><<<dim3(M / 128, RR / 128), 256>>>(
        x, freq, nullptr, M, RR, DD);

    // 5) sequential scan over S -> g_acc; final_state appended to out if room
    long long need_fs = (long long)BB * SS * DD + BB * RR;
    float* fs_ptr = ((long long)out_size >= need_fs) ? (out + (size_t)BB * SS * DD)
                                                     : nullptr;
    scan_kernel<<<(BB * RR) / 256, 256>>>(prev_st, fs_ptr);

    // 6) GEMM2: output = acc @ out_w^T  (M x D)
    sgemm_f32x2_kernel<2><<<dim3(M / 128, DD / 128), 256>>>(
        nullptr, out_w, out, M, DD, RR);
}

// round 5
// speedup vs baseline: 1.9019x; 1.9019x over previous
#include <cuda_runtime.h>
#include <cuda_bf16.h>
#include <cstdint>
#include <math.h>

// ---------------------------------------------------------------------------
// StableResonatorBank: B=8, S=4096, D=1024, R=256   (mma.sync bf16x3 version)
//   resonance = (x/||x||) . (freq/||freq||)^T   [GEMM1 M=32768,N=256,K=1024]
//   gate/retention from column-mean of x
//   signal = resonance*gate ; scan over S ; output = acc @ out_w^T
//                                               [GEMM2 M=32768,N=1024,K=256]
// fp32 operands split into bf16 hi+lo; 3 mma.sync per fragment (hh+hl+lh).
// tcgen05 unavailable (harness compiles PTX for compute_103, no 'a' target).
// ---------------------------------------------------------------------------

#define BB 8
#define SS 4096
#define DD 1024
#define RR 256
#define SEGS 16
#define MTOT (BB * SS)   // 32768

// ---------------- static device scratch (256B aligned for vector ops) ------
__device__ __align__(256) __nv_bfloat16 g_xh[MTOT * DD];
__device__ __align__(256) __nv_bfloat16 g_xl[MTOT * DD];
__device__ __align__(256) __nv_bfloat16 g_fh[RR * DD];
__device__ __align__(256) __nv_bfloat16 g_fl[RR * DD];
__device__ __align__(256) __nv_bfloat16 g_ah[MTOT * RR];
__device__ __align__(256) __nv_bfloat16 g_al[MTOT * RR];
__device__ __align__(256) __nv_bfloat16 g_wh[DD * RR];
__device__ __align__(256) __nv_bfloat16 g_wl[DD * RR];
__device__ __align__(256) float g_signal[MTOT * RR];   // 33.5 MB
__device__ float g_xm_part[BB * SEGS * DD];
__device__ float g_xm[BB * DD];
__device__ float g_gate[BB * RR];
__device__ float g_ret[BB * RR];

// ---------------- PTX helpers (all baseline PTX, no 'a' features) ----------
#define SWZ64(off) ((off) ^ (((off) >> 3) & 0x30))   // 64B-row XOR swizzle

__device__ __forceinline__ void cp16(uint32_t saddr, const void* g) {
    asm volatile("cp.async.cg.shared.global [%0], [%1], 16;"
                 :: "r"(saddr), "l"(g) : "memory");
}
#define CP_COMMIT() asm volatile("cp.async.commit_group;" ::: "memory")
#define CP_WAIT(n)  asm volatile("cp.async.wait_group %0;" :: "n"(n) : "memory")

__device__ __forceinline__ void ldsm_x4(uint32_t (&r)[4], uint32_t addr) {
    asm volatile("ldmatrix.sync.aligned.m8n8.x4.shared.b16 {%0,%1,%2,%3}, [%4];"
                 : "=r"(r[0]), "=r"(r[1]), "=r"(r[2]), "=r"(r[3]) : "r"(addr));
}
__device__ __forceinline__ void mma_bf16(float (&c)[4], const uint32_t (&a)[4],
                                         uint32_t b0, uint32_t b1) {
    asm volatile("mma.sync.aligned.m16n8k16.row.col.f32.bf16.bf16.f32 "
                 "{%0,%1,%2,%3}, {%4,%5,%6,%7}, {%8,%9}, {%0,%1,%2,%3};"
                 : "+f"(c[0]), "+f"(c[1]), "+f"(c[2]), "+f"(c[3])
                 : "r"(a[0]), "r"(a[1]), "r"(a[2]), "r"(a[3]), "r"(b0), "r"(b1));
}

// ---------------- conversion: fp32 rows -> (normalized) bf16 hi/lo ---------
// DST: 0 freq(norm,1024), 1 x(norm,1024), 2 out_w(no norm,256)
template <int DST>
__global__ void conv_kernel(const float* __restrict__ src, int rows) {
    const int cols = (DST == 2) ? RR : DD;
    int warp = (blockIdx.x * blockDim.x + threadIdx.x) >> 5;
    int lane = threadIdx.x & 31;
    if (warp >= rows) return;
    const float4* p = (const float4*)(src + (size_t)warp * cols);
    const int n4 = cols / 128;
    float4 v[8];
    float ssum = 0.f;
#pragma unroll
    for (int i = 0; i < n4; i++) {
        v[i] = p[lane + 32 * i];
        ssum += v[i].x * v[i].x + v[i].y * v[i].y + v[i].z * v[i].z + v[i].w * v[i].w;
    }
    float inv = 1.0f;
    if (DST != 2) {
#pragma unroll
        for (int o = 16; o > 0; o >>= 1) ssum += __shfl_xor_sync(0xFFFFFFFFu, ssum, o);
        inv = 1.0f / fmaxf(sqrtf(ssum), 1e-12f);
    }
    __nv_bfloat16* dh = (DST == 0) ? g_fh : (DST == 1) ? g_xh : g_wh;
    __nv_bfloat16* dl = (DST == 0) ? g_fl : (DST == 1) ? g_xl : g_wl;
#pragma unroll
    for (int i = 0; i < n4; i++) {
        float f[4] = {v[i].x * inv, v[i].y * inv, v[i].z * inv, v[i].w * inv};
        ushort4 wh, wl;
        unsigned short* ph = &wh.x;
        unsigned short* pl = &wl.x;
#pragma unroll
        for (int j = 0; j < 4; j++) {
            __nv_bfloat16 h = __float2bfloat16(f[j]);
            __nv_bfloat16 l = __float2bfloat16(f[j] - __bfloat162float(h));
            ph[j] = __bfloat16_as_ushort(h);
            pl[j] = __bfloat16_as_ushort(l);
        }
        size_t off = (size_t)warp * cols + (size_t)(lane + 32 * i) * 4;
        *(ushort4*)(dh + off) = wh;
        *(ushort4*)(dl + off) = wl;
    }
}

// ---------------- column means of x (two-phase, deterministic) -------------
__global__ void mean_partial_kernel(const float* __restrict__ x) {
    int d = blockIdx.x * 256 + threadIdx.x;
    int seg = blockIdx.y, b = blockIdx.z;
    const int L = SS / SEGS;
    const float* p = x + ((size_t)b * SS + (size_t)seg * L) * DD + d;
    float s = 0.f;
#pragma unroll 4
    for (int t = 0; t < L; t++) s += p[(size_t)t * DD];
    g_xm_part[(b * SEGS + seg) * DD + d] = s;
}

__global__ void mean_reduce_kernel() {
    int i = blockIdx.x * 256 + threadIdx.x;
    float s = 0.f;
#pragma unroll
    for (int seg = 0; seg < SEGS; seg++)
        s += g_xm_part[((i >> 10) * SEGS + seg) * DD + (i & (DD - 1))];
    g_xm[i] = s * (1.0f / (float)SS);
}

// ---------------- gate / retention (one warp per (b,r)) --------------------
__global__ void gate_ret_kernel(const float* __restrict__ gate_w,
                                const float* __restrict__ gate_bias,
                                const float* __restrict__ ret_w,
                                const float* __restrict__ ret_bias) {
    int warp = (blockIdx.x * blockDim.x + threadIdx.x) >> 5;
    int lane = threadIdx.x & 31;
    if (warp >= BB * RR) return;
    int b = warp >> 8, r = warp & (RR - 1);
    const float* xm = g_xm + (size_t)b * DD;
    const float* gw = gate_w + (size_t)r * DD;
    const float* rw = ret_w + (size_t)r * DD;
    float s1 = 0.f, s2 = 0.f;
#pragma unroll 8
    for (int i = lane; i < DD; i += 32) {
        float xv = xm[i];
        s1 = fmaf(xv, gw[i], s1);
        s2 = fmaf(xv, rw[i], s2);
    }
#pragma unroll
    for (int o = 16; o > 0; o >>= 1) {
        s1 += __shfl_xor_sync(0xFFFFFFFFu, s1, o);
        s2 += __shfl_xor_sync(0xFFFFFFFFu, s2, o);
    }
    if (lane == 0) {
        float gs = 1.0f / (1.0f + expf(-(s1 + gate_bias[r])));
        g_gate[warp] = (gs >= 0.001f) ? gs : 0.0f;
        g_ret[warp] = 1.0f / (1.0f + expf(-(s2 + ret_bias[r])));
    }
}

// ---------------- mma.sync bf16x3 GEMM: C[M,N] = A[M,K]*B[N,K]^T -----------
// 128x128 CTA tile, 8 warps (warp tile 64x32), K-chunks of 32, 2-stage
// cp.async double buffering. MODE 1: C=g_signal (*gate). MODE 2: C=param.
#define TILE_B  8192               // one 128x32 bf16 tile, swizzled 64B rows
#define STAGE_B (4 * TILE_B)       // Ah, Al, Bh, Bl
#define SMEM_B  (2 * STAGE_B)      // 64 KB

__device__ __forceinline__ void stage_tile(const __nv_bfloat16* __restrict__ src,
                                           size_t row0, int K, int k0,
                                           uint32_t sbase, int tid) {
#pragma unroll
    for (int it = 0; it < 2; it++) {
        int idx = tid + it * 256;          // 0..511
        int row = idx >> 2, u = idx & 3;
        cp16(sbase + SWZ64(row * 64 + u * 16),
             src + (row0 + row) * (size_t)K + k0 + u * 8);
    }
}

template <int MODE>
__global__ __launch_bounds__(256) void tc_gemm(float* __restrict__ Cout,
                                               int N, int K) {
    extern __shared__ char smem[];
    uint32_t sb = (uint32_t)__cvta_generic_to_shared(smem);
    int tid = threadIdx.x;
    int lane = tid & 31, wid = tid >> 5;
    int wm = wid >> 2, wn = wid & 3;       // warp tile: rows wm*64, cols wn*32
    int bm = blockIdx.x, bn = blockIdx.y;

    const __nv_bfloat16* Ah = (MODE == 1) ? g_xh : g_ah;
    const __nv_bfloat16* Al = (MODE == 1) ? g_xl : g_al;
    const __nv_bfloat16* Bh = (MODE == 1) ? g_fh : g_wh;
    const __nv_bfloat16* Bl = (MODE == 1) ? g_fl : g_wl;

    size_t aRow0 = (size_t)bm * 128, bRow0 = (size_t)bn * 128;

    float acc[4][4][4];
#pragma unroll
    for (int i = 0; i < 4; i++)
#pragma unroll
        for (int j = 0; j < 4; j++)
#pragma unroll
            for (int q = 0; q < 4; q++) acc[i][j][q] = 0.f;

    const int nch = K / 32;
    // prefetch chunk 0 into stage 0
    stage_tile(Ah, aRow0, K, 0, sb + 0 * TILE_B, tid);
    stage_tile(Al, aRow0, K, 0, sb + 1 * TILE_B, tid);
    stage_tile(Bh, bRow0, K, 0, sb + 2 * TILE_B, tid);
    stage_tile(Bl, bRow0, K, 0, sb + 3 * TILE_B, tid);
    CP_COMMIT();

    // precomputed ldmatrix lane offsets (within a tile, before k-sub offset)
    int aoff0 = (lane & 15) * 64 + (lane >> 4) * 16;              // + row base
    int grp = lane >> 3, wtn = lane & 7;
    int boff0 = ((grp >> 1) * 8 + wtn) * 64 + (grp & 1) * 16;     // + n base

    for (int c = 0; c < nch; c++) {
        if (c + 1 < nch) {
            uint32_t st = sb + ((c + 1) & 1) * STAGE_B;
            int k0 = (c + 1) * 32;
            stage_tile(Ah, aRow0, K, k0, st + 0 * TILE_B, tid);
            stage_tile(Al, aRow0, K, k0, st + 1 * TILE_B, tid);
            stage_tile(Bh, bRow0, K, k0, st + 2 * TILE_B, tid);
            stage_tile(Bl, bRow0, K, k0, st + 3 * TILE_B, tid);
            CP_COMMIT();
            CP_WAIT(1);
        } else {
            CP_WAIT(0);
        }
        __syncthreads();

        uint32_t st = sb + (c & 1) * STAGE_B;
        uint32_t sAh = st, sAl = st + TILE_B, sBh = st + 2 * TILE_B, sBl = st + 3 * TILE_B;
#pragma unroll
        for (int ks = 0; ks < 2; ks++) {
            uint32_t af_h[4][4], af_l[4][4];
#pragma unroll
            for (int i = 0; i < 4; i++) {
                int off = SWZ64((wm * 64 + i * 16) * 64 + aoff0 + ks * 32);
                ldsm_x4(af_h[i], sAh + off);
                ldsm_x4(af_l[i], sAl + off);
            }
            uint32_t bf_h[2][4], bf_l[2][4];
#pragma unroll
            for (int h = 0; h < 2; h++) {
                int off = SWZ64((wn * 32 + h * 16) * 64 + boff0 + ks * 32);
                ldsm_x4(bf_h[h], sBh + off);
                ldsm_x4(bf_l[h], sBl + off);
            }
#pragma unroll
            for (int i = 0; i < 4; i++)
#pragma unroll
                for (int j = 0; j < 4; j++) {
                    int h = j >> 1, q = (j & 1) * 2;
                    mma_bf16(acc[i][j], af_h[i], bf_h[h][q], bf_h[h][q + 1]);
                    mma_bf16(acc[i][j], af_h[i], bf_l[h][q], bf_l[h][q + 1]);
                    mma_bf16(acc[i][j], af_l[i], bf_h[h][q], bf_h[h][q + 1]);
                }
        }
        __syncthreads();
    }

    float* C = (MODE == 1) ? g_signal : Cout;
    int bb = bm >> 5;   // batch index of this row tile (4096/128 = 32)
#pragma unroll
    for (int i = 0; i < 4; i++) {
        int m0 = bm * 128 + wm * 64 + i * 16 + (lane >> 2);
#pragma unroll
        for (int j = 0; j < 4; j++) {
            int n0 = bn * 128 + wn * 32 + j * 8 + (lane & 3) * 2;
            float g0 = 1.f, g1 = 1.f;
            if (MODE == 1) {
                g0 = g_gate[bb * RR + n0];
                g1 = g_gate[bb * RR + n0 + 1];
            }
            *(float2*)(C + (size_t)m0 * N + n0) =
                make_float2(acc[i][j][0] * g0, acc[i][j][1] * g1);
            *(float2*)(C + (size_t)(m0 + 8) * N + n0) =
                make_float2(acc[i][j][2] * g0, acc[i][j][3] * g1);
        }
    }
}

// ---------------- scan: acc_t = sig_t + acc_{t-1}*retention ----------------
__global__ void scan_kernel(const float* __restrict__ prev_state,
                            float* __restrict__ final_state_out) {
    int c = blockIdx.x * blockDim.x + threadIdx.x;  // 0..2047
    if (c >= BB * RR) return;
    int b = c >> 8, r = c & (RR - 1);
    float st = prev_state[c];
    float ret = g_ret[c];
    size_t base = (size_t)b * SS * RR + r;
#pragma unroll 16
    for (int t = 0; t < SS; t++) {
        size_t pos = base + (size_t)t * RR;
        float v = g_signal[pos];
        st = fmaf(st, ret, v);
        __nv_bfloat16 h = __float2bfloat16(st);
        g_ah[pos] = h;
        g_al[pos] = __float2bfloat16(st - __bfloat162float(h));
    }
    if (final_state_out) final_state_out[c] = st;
}

// ---------------------------------------------------------------------------
extern "C" void kernel_launch(void* const* d_in, const int* in_sizes, int n_in,
                              void* d_out, int out_size) {
    const float* x         = (const float*)d_in[0];
    const float* prev_st   = (const float*)d_in[1];
    const float* freq      = (const float*)d_in[2];
    const float* ret_bias  = (const float*)d_in[3];
    const float* ret_w     = (const float*)d_in[4];
    const float* gate_w    = (const float*)d_in[5];
    const float* gate_bias = (const float*)d_in[6];
    const float* out_w     = (const float*)d_in[7];
    float* out = (float*)d_out;

    cudaFuncSetAttribute(tc_gemm<1>, cudaFuncAttributeMaxDynamicSharedMemorySize, SMEM_B);
    cudaFuncSetAttribute(tc_gemm<2>, cudaFuncAttributeMaxDynamicSharedMemorySize, SMEM_B);

    conv_kernel<0><<<RR / 8, 256>>>(freq, RR);                                   // 1
    conv_kernel<1><<<MTOT / 8, 256>>>(x, MTOT);                                  // 2
    mean_partial_kernel<<<dim3(DD / 256, SEGS, BB), 256>>>(x);                   // 3
    mean_reduce_kernel<<<(BB * DD) / 256, 256>>>();                              // 4
    gate_ret_kernel<<<(BB * RR) / 8, 256>>>(gate_w, gate_bias, ret_w, ret_bias); // 5
    // 6) GEMM1 (ncu -s 5 -c 1 profiles this launch)
    tc_gemm<1><<<dim3(MTOT / 128, RR / 128), 256, SMEM_B>>>(nullptr, RR, DD);    // 6
    long long need_fs = (long long)MTOT * DD + BB * RR;
    float* fs_ptr = ((long long)out_size >= need_fs) ? (out + (size_t)MTOT * DD) : nullptr;
    scan_kernel<<<64, 32>>>(prev_st, fs_ptr);                                    // 7
    conv_kernel<2><<<DD / 8, 256>>>(out_w, DD);                                  // 8
    tc_gemm<2><<<dim3(MTOT / 128, DD / 128), 256, SMEM_B>>>(out, DD, RR);        // 9
}

// round 9
// speedup vs baseline: 1.9098x; 1.0042x over previous
#include <cuda_runtime.h>
#include <cuda_bf16.h>
#include <cstdint>
#include <math.h>

// ---------------------------------------------------------------------------
// StableResonatorBank: B=8, S=4096, D=1024, R=256   (mma.sync bf16x3 version)
// GEMM1 M=32768,N=256,K=1024 ; GEMM2 M=32768,N=1024,K=256
// fp32 operands split into bf16 hi+lo; 3 mma.sync per fragment (hh+hl+lh).
// Gate fused into scan (lets GEMM1 run as launch #4 -> ncu capture slot).
// ---------------------------------------------------------------------------

#define BB 8
#define SS 4096
#define DD 1024
#define RR 256
#define SEGS 16
#define MTOT (BB * SS)   // 32768

__device__ __align__(256) __nv_bfloat16 g_xh[MTOT * DD];
__device__ __align__(256) __nv_bfloat16 g_xl[MTOT * DD];
__device__ __align__(256) __nv_bfloat16 g_fh[RR * DD];
__device__ __align__(256) __nv_bfloat16 g_fl[RR * DD];
__device__ __align__(256) __nv_bfloat16 g_ah[MTOT * RR];
__device__ __align__(256) __nv_bfloat16 g_al[MTOT * RR];
__device__ __align__(256) __nv_bfloat16 g_wh[DD * RR];
__device__ __align__(256) __nv_bfloat16 g_wl[DD * RR];
__device__ __align__(256) float g_signal[MTOT * RR];   // 33.5 MB
__device__ float g_xm_part[BB * SEGS * DD];
__device__ float g_xm[BB * DD];
__device__ float g_gate[BB * RR];
__device__ float g_ret[BB * RR];

// ---------------- PTX helpers (baseline PTX only) --------------------------
#define SWZ64(off) ((off) ^ (((off) >> 3) & 0x30))   // 64B-row XOR swizzle

__device__ __forceinline__ void cp16(uint32_t saddr, const void* g) {
    asm volatile("cp.async.cg.shared.global [%0], [%1], 16;"
                 :: "r"(saddr), "l"(g) : "memory");
}
#define CP_COMMIT() asm volatile("cp.async.commit_group;" ::: "memory")
#define CP_WAIT(n)  asm volatile("cp.async.wait_group %0;" :: "n"(n) : "memory")

__device__ __forceinline__ void ldsm_x4(uint32_t (&r)[4], uint32_t addr) {
    asm volatile("ldmatrix.sync.aligned.m8n8.x4.shared.b16 {%0,%1,%2,%3}, [%4];"
                 : "=r"(r[0]), "=r"(r[1]), "=r"(r[2]), "=r"(r[3]) : "r"(addr));
}
__device__ __forceinline__ void mma_bf16(float (&c)[4], const uint32_t (&a)[4],
                                         uint32_t b0, uint32_t b1) {
    asm volatile("mma.sync.aligned.m16n8k16.row.col.f32.bf16.bf16.f32 "
                 "{%0,%1,%2,%3}, {%4,%5,%6,%7}, {%8,%9}, {%0,%1,%2,%3};"
                 : "+f"(c[0]), "+f"(c[1]), "+f"(c[2]), "+f"(c[3])
                 : "r"(a[0]), "r"(a[1]), "r"(a[2]), "r"(a[3]), "r"(b0), "r"(b1));
}

// ---------------- conversion: fp32 rows -> (normalized) bf16 hi/lo ---------
template <int DST>   // 0 freq(norm,1024), 1 x(norm,1024), 2 out_w(no norm,256)
__global__ void conv_kernel(const float* __restrict__ src, int rows) {
    const int cols = (DST == 2) ? RR : DD;
    int warp = (blockIdx.x * blockDim.x + threadIdx.x) >> 5;
    int lane = threadIdx.x & 31;
    if (warp >= rows) return;
    const float4* p = (const float4*)(src + (size_t)warp * cols);
    const int n4 = cols / 128;
    float4 v[8];
    float ssum = 0.f;
#pragma unroll
    for (int i = 0; i < n4; i++) {
        v[i] = p[lane + 32 * i];
        ssum += v[i].x * v[i].x + v[i].y * v[i].y + v[i].z * v[i].z + v[i].w * v[i].w;
    }
    float inv = 1.0f;
    if (DST != 2) {
#pragma unroll
        for (int o = 16; o > 0; o >>= 1) ssum += __shfl_xor_sync(0xFFFFFFFFu, ssum, o);
        inv = 1.0f / fmaxf(sqrtf(ssum), 1e-12f);
    }
    __nv_bfloat16* dh = (DST == 0) ? g_fh : (DST == 1) ? g_xh : g_wh;
    __nv_bfloat16* dl = (DST == 0) ? g_fl : (DST == 1) ? g_xl : g_wl;
#pragma unroll
    for (int i = 0; i < n4; i++) {
        float f[4] = {v[i].x * inv, v[i].y * inv, v[i].z * inv, v[i].w * inv};
        ushort4 wh, wl;
        unsigned short* ph = &wh.x;
        unsigned short* pl = &wl.x;
#pragma unroll
        for (int j = 0; j < 4; j++) {
            __nv_bfloat16 h = __float2bfloat16(f[j]);
            __nv_bfloat16 l = __float2bfloat16(f[j] - __bfloat162float(h));
            ph[j] = __bfloat16_as_ushort(h);
            pl[j] = __bfloat16_as_ushort(l);
        }
        size_t off = (size_t)warp * cols + (size_t)(lane + 32 * i) * 4;
        *(ushort4*)(dh + off) = wh;
        *(ushort4*)(dl + off) = wl;
    }
}

// ---------------- column means of x (two-phase, deterministic) -------------
__global__ void mean_partial_kernel(const float* __restrict__ x) {
    int d = blockIdx.x * 256 + threadIdx.x;
    int seg = blockIdx.y, b = blockIdx.z;
    const int L = SS / SEGS;
    const float* p = x + ((size_t)b * SS + (size_t)seg * L) * DD + d;
    float s = 0.f;
#pragma unroll 4
    for (int t = 0; t < L; t++) s += p[(size_t)t * DD];
    g_xm_part[(b * SEGS + seg) * DD + d] = s;
}

__global__ void mean_reduce_kernel() {
    int i = blockIdx.x * 256 + threadIdx.x;
    float s = 0.f;
#pragma unroll
    for (int seg = 0; seg < SEGS; seg++)
        s += g_xm_part[((i >> 10) * SEGS + seg) * DD + (i & (DD - 1))];
    g_xm[i] = s * (1.0f / (float)SS);
}

// ---------------- gate / retention (one warp per (b,r)) --------------------
__global__ void gate_ret_kernel(const float* __restrict__ gate_w,
                                const float* __restrict__ gate_bias,
                                const float* __restrict__ ret_w,
                                const float* __restrict__ ret_bias) {
    int warp = (blockIdx.x * blockDim.x + threadIdx.x) >> 5;
    int lane = threadIdx.x & 31;
    if (warp >= BB * RR) return;
    int b = warp >> 8, r = warp & (RR - 1);
    const float* xm = g_xm + (size_t)b * DD;
    const float* gw = gate_w + (size_t)r * DD;
    const float* rw = ret_w + (size_t)r * DD;
    float s1 = 0.f, s2 = 0.f;
#pragma unroll 8
    for (int i = lane; i < DD; i += 32) {
        float xv = xm[i];
        s1 = fmaf(xv, gw[i], s1);
        s2 = fmaf(xv, rw[i], s2);
    }
#pragma unroll
    for (int o = 16; o > 0; o >>= 1) {
        s1 += __shfl_xor_sync(0xFFFFFFFFu, s1, o);
        s2 += __shfl_xor_sync(0xFFFFFFFFu, s2, o);
    }
    if (lane == 0) {
        float gs = 1.0f / (1.0f + expf(-(s1 + gate_bias[r])));
        g_gate[warp] = (gs >= 0.001f) ? gs : 0.0f;
        g_ret[warp] = 1.0f / (1.0f + expf(-(s2 + ret_bias[r])));
    }
}

// ---------------- mma.sync bf16x3 GEMM: C[M,N] = A[M,K]*B[N,K]^T -----------
// 128x128 CTA tile, 16 warps (warp tile 32x32), K-chunks of 32, 2-stage
// cp.async double buffering, ONE __syncthreads per chunk.
#define TILE_B  8192               // one 128x32 bf16 tile, swizzled 64B rows
#define STAGE_B (4 * TILE_B)       // Ah, Al, Bh, Bl
#define SMEM_B  (2 * STAGE_B)      // 64 KB

__device__ __forceinline__ void stage_tile(const __nv_bfloat16* __restrict__ src,
                                           size_t row0, int K, int k0,
                                           uint32_t sbase, int tid) {
    int row = tid >> 2, u = tid & 3;          // 512 threads: one 16B each
    cp16(sbase + SWZ64(row * 64 + u * 16),
         src + (row0 + row) * (size_t)K + k0 + u * 8);
}

template <int MODE>
__global__ __launch_bounds__(512) void tc_gemm(float* __restrict__ Cout,
                                               int N, int K) {
    extern __shared__ char smem[];
    uint32_t sb = (uint32_t)__cvta_generic_to_shared(smem);
    int tid = threadIdx.x;
    int lane = tid & 31, wid = tid >> 5;
    int wm = wid >> 2, wn = wid & 3;          // warp tile rows wm*32, cols wn*32
    int bm = blockIdx.x, bn = blockIdx.y;

    const __nv_bfloat16* Ah = (MODE == 1) ? g_xh : g_ah;
    const __nv_bfloat16* Al = (MODE == 1) ? g_xl : g_al;
    const __nv_bfloat16* Bh = (MODE == 1) ? g_fh : g_wh;
    const __nv_bfloat16* Bl = (MODE == 1) ? g_fl : g_wl;

    size_t aRow0 = (size_t)bm * 128, bRow0 = (size_t)bn * 128;

    float acc[2][4][4];
#pragma unroll
    for (int i = 0; i < 2; i++)
#pragma unroll
        for (int j = 0; j < 4; j++)
#pragma unroll
            for (int q = 0; q < 4; q++) acc[i][j][q] = 0.f;

    const int nch = K / 32;
    // prologue: stage chunk 0
    stage_tile(Ah, aRow0, K, 0, sb + 0 * TILE_B, tid);
    stage_tile(Al, aRow0, K, 0, sb + 1 * TILE_B, tid);
    stage_tile(Bh, bRow0, K, 0, sb + 2 * TILE_B, tid);
    stage_tile(Bl, bRow0, K, 0, sb + 3 * TILE_B, tid);
    CP_COMMIT();
    CP_WAIT(0);
    __syncthreads();

    // ldmatrix lane offsets
    int aoff0 = (lane & 15) * 64 + (lane >> 4) * 16;
    int grp = lane >> 3, wtn = lane & 7;
    int boff0 = ((grp >> 1) * 8 + wtn) * 64 + (grp & 1) * 16;

    for (int c = 0; c < nch; c++) {
        // issue loads for c+1 (safe: target buffer's readers finished before
        // the barrier that ended iteration c-1)
        if (c + 1 < nch) {
            uint32_t st = sb + ((c + 1) & 1) * STAGE_B;
            int k0 = (c + 1) * 32;
            stage_tile(Ah, aRow0, K, k0, st + 0 * TILE_B, tid);
            stage_tile(Al, aRow0, K, k0, st + 1 * TILE_B, tid);
            stage_tile(Bh, bRow0, K, k0, st + 2 * TILE_B, tid);
            stage_tile(Bl, bRow0, K, k0, st + 3 * TILE_B, tid);
            CP_COMMIT();
        }

        uint32_t st = sb + (c & 1) * STAGE_B;
        uint32_t sAh = st, sAl = st + TILE_B, sBh = st + 2 * TILE_B, sBl = st + 3 * TILE_B;
#pragma unroll
        for (int ks = 0; ks < 2; ks++) {
            uint32_t af_h[2][4], af_l[2][4];
#pragma unroll
            for (int i = 0; i < 2; i++) {
                int off = SWZ64((wm * 32 + i * 16) * 64 + aoff0 + ks * 32);
                ldsm_x4(af_h[i], sAh + off);
                ldsm_x4(af_l[i], sAl + off);
            }
            uint32_t bf_h[2][4], bf_l[2][4];
#pragma unroll
            for (int h = 0; h < 2; h++) {
                int off = SWZ64((wn * 32 + h * 16) * 64 + boff0 + ks * 32);
                ldsm_x4(bf_h[h], sBh + off);
                ldsm_x4(bf_l[h], sBl + off);
            }
#pragma unroll
            for (int i = 0; i < 2; i++)
#pragma unroll
                for (int j = 0; j < 4; j++) {
                    int h = j >> 1, q = (j & 1) * 2;
                    mma_bf16(acc[i][j], af_h[i], bf_h[h][q], bf_h[h][q + 1]);
                    mma_bf16(acc[i][j], af_h[i], bf_l[h][q], bf_l[h][q + 1]);
                    mma_bf16(acc[i][j], af_l[i], bf_h[h][q], bf_h[h][q + 1]);
                }
        }
        if (c + 1 < nch) CP_WAIT(0);
        __syncthreads();
    }

    float* C = (MODE == 1) ? g_signal : Cout;
#pragma unroll
    for (int i = 0; i < 2; i++) {
        int m0 = bm * 128 + wm * 32 + i * 16 + (lane >> 2);
#pragma unroll
        for (int j = 0; j < 4; j++) {
            int n0 = bn * 128 + wn * 32 + j * 8 + (lane & 3) * 2;
            *(float2*)(C + (size_t)m0 * N + n0) = make_float2(acc[i][j][0], acc[i][j][1]);
            *(float2*)(C + (size_t)(m0 + 8) * N + n0) = make_float2(acc[i][j][2], acc[i][j][3]);
        }
    }
}

// ---------------- scan: acc_t = gate*sig_t + acc_{t-1}*retention -----------
__global__ void scan_kernel(const float* __restrict__ prev_state,
                            float* __restrict__ final_state_out) {
    int c = blockIdx.x * blockDim.x + threadIdx.x;  // 0..2047
    if (c >= BB * RR) return;
    int b = c >> 8, r = c & (RR - 1);
    float st = prev_state[c];
    float ret = g_ret[c];
    float gate = g_gate[c];
    size_t base = (size_t)b * SS * RR + r;
#pragma unroll 16
    for (int t = 0; t < SS; t++) {
        size_t pos = base + (size_t)t * RR;
        float v = g_signal[pos] * gate;
        st = fmaf(st, ret, v);
        __nv_bfloat16 h = __float2bfloat16(st);
        g_ah[pos] = h;
        g_al[pos] = __float2bfloat16(st - __bfloat162float(h));
    }
    if (final_state_out) final_state_out[c] = st;
}

// ---------------------------------------------------------------------------
extern "C" void kernel_launch(void* const* d_in, const int* in_sizes, int n_in,
                              void* d_out, int out_size) {
    const float* x         = (const float*)d_in[0];
    const float* prev_st   = (const float*)d_in[1];
    const float* freq      = (const float*)d_in[2];
    const float* ret_bias  = (const float*)d_in[3];
    const float* ret_w     = (const float*)d_in[4];
    const float* gate_w    = (const float*)d_in[5];
    const float* gate_bias = (const float*)d_in[6];
    const float* out_w     = (const float*)d_in[7];
    float* out = (float*)d_out;

    cudaFuncSetAttribute(tc_gemm<1>, cudaFuncAttributeMaxDynamicSharedMemorySize, SMEM_B);
    cudaFuncSetAttribute(tc_gemm<2>, cudaFuncAttributeMaxDynamicSharedMemorySize, SMEM_B);

    conv_kernel<0><<<RR / 8, 256>>>(freq, RR);                                   // 1
    conv_kernel<1><<<MTOT / 8, 256>>>(x, MTOT);                                  // 2
    mean_partial_kernel<<<dim3(DD / 256, SEGS, BB), 256>>>(x);                   // 3
    // 4) GEMM1 — my 4th launch = ncu's captured launch (skip-5 incl. 2 harness)
    tc_gemm<1><<<dim3(MTOT / 128, RR / 128), 512, SMEM_B>>>(nullptr, RR, DD);    // 4
    mean_reduce_kernel<<<(BB * DD) / 256, 256>>>();                              // 5
    gate_ret_kernel<<<(BB * RR) / 8, 256>>>(gate_w, gate_bias, ret_w, ret_bias); // 6
    long long need_fs = (long long)MTOT * DD + BB * RR;
    float* fs_ptr = ((long long)out_size >= need_fs) ? (out + (size_t)MTOT * DD) : nullptr;
    scan_kernel<<<64, 32>>>(prev_st, fs_ptr);                                    // 7 (64 SMs)
    conv_kernel<2><<<DD / 8, 256>>>(out_w, DD);                                  // 8
    tc_gemm<2><<<dim3(MTOT / 128, DD / 128), 512, SMEM_B>>>(out, DD, RR);        // 9
}

// round 14
// speedup vs baseline: 1.9125x; 1.0014x over previous
#include <cuda_runtime.h>
#include <cuda_bf16.h>
#include <cstdint>
#include <math.h>

// ---------------------------------------------------------------------------
// StableResonatorBank: B=8, S=4096, D=1024, R=256   (mma.sync bf16x3 version)
// GEMM1 M=32768,N=256,K=1024 ; GEMM2 M=32768,N=1024,K=256
// fp32 operands split into bf16 hi+lo; 3 mma.sync per fragment (hh+hl+lh).
// Grid transposed (bn fastest) so CTAs sharing an A tile run in one wave ->
// A read once from DRAM, served to siblings from L2.
// ---------------------------------------------------------------------------

#define BB 8
#define SS 4096
#define DD 1024
#define RR 256
#define SEGS 16
#define MTOT (BB * SS)   // 32768

__device__ __align__(256) __nv_bfloat16 g_xh[MTOT * DD];
__device__ __align__(256) __nv_bfloat16 g_xl[MTOT * DD];
__device__ __align__(256) __nv_bfloat16 g_fh[RR * DD];
__device__ __align__(256) __nv_bfloat16 g_fl[RR * DD];
__device__ __align__(256) __nv_bfloat16 g_ah[MTOT * RR];
__device__ __align__(256) __nv_bfloat16 g_al[MTOT * RR];
__device__ __align__(256) __nv_bfloat16 g_wh[DD * RR];
__device__ __align__(256) __nv_bfloat16 g_wl[DD * RR];
__device__ __align__(256) float g_signal[MTOT * RR];   // 33.5 MB
__device__ float g_xm_part[BB * SEGS * DD];
__device__ float g_xm[BB * DD];
__device__ float g_gate[BB * RR];
__device__ float g_ret[BB * RR];

// ---------------- PTX helpers (baseline PTX only) --------------------------
#define SWZ64(off) ((off) ^ (((off) >> 3) & 0x30))   // 64B-row XOR swizzle

__device__ __forceinline__ void cp16(uint32_t saddr, const void* g) {
    asm volatile("cp.async.cg.shared.global [%0], [%1], 16;"
                 :: "r"(saddr), "l"(g) : "memory");
}
#define CP_COMMIT() asm volatile("cp.async.commit_group;" ::: "memory")
#define CP_WAIT(n)  asm volatile("cp.async.wait_group %0;" :: "n"(n) : "memory")

__device__ __forceinline__ void ldsm_x4(uint32_t (&r)[4], uint32_t addr) {
    asm volatile("ldmatrix.sync.aligned.m8n8.x4.shared.b16 {%0,%1,%2,%3}, [%4];"
                 : "=r"(r[0]), "=r"(r[1]), "=r"(r[2]), "=r"(r[3]) : "r"(addr));
}
__device__ __forceinline__ void mma_bf16(float (&c)[4], const uint32_t (&a)[4],
                                         uint32_t b0, uint32_t b1) {
    asm volatile("mma.sync.aligned.m16n8k16.row.col.f32.bf16.bf16.f32 "
                 "{%0,%1,%2,%3}, {%4,%5,%6,%7}, {%8,%9}, {%0,%1,%2,%3};"
                 : "+f"(c[0]), "+f"(c[1]), "+f"(c[2]), "+f"(c[3])
                 : "r"(a[0]), "r"(a[1]), "r"(a[2]), "r"(a[3]), "r"(b0), "r"(b1));
}

// ---------------- conversion: fp32 rows -> (normalized) bf16 hi/lo ---------
template <int DST>   // 0 freq(norm,1024), 1 x(norm,1024), 2 out_w(no norm,256)
__global__ void conv_kernel(const float* __restrict__ src, int rows) {
    const int cols = (DST == 2) ? RR : DD;
    int warp = (blockIdx.x * blockDim.x + threadIdx.x) >> 5;
    int lane = threadIdx.x & 31;
    if (warp >= rows) return;
    const float4* p = (const float4*)(src + (size_t)warp * cols);
    const int n4 = cols / 128;
    float4 v[8];
    float ssum = 0.f;
#pragma unroll
    for (int i = 0; i < n4; i++) {
        v[i] = p[lane + 32 * i];
        ssum += v[i].x * v[i].x + v[i].y * v[i].y + v[i].z * v[i].z + v[i].w * v[i].w;
    }
    float inv = 1.0f;
    if (DST != 2) {
#pragma unroll
        for (int o = 16; o > 0; o >>= 1) ssum += __shfl_xor_sync(0xFFFFFFFFu, ssum, o);
        inv = 1.0f / fmaxf(sqrtf(ssum), 1e-12f);
    }
    __nv_bfloat16* dh = (DST == 0) ? g_fh : (DST == 1) ? g_xh : g_wh;
    __nv_bfloat16* dl = (DST == 0) ? g_fl : (DST == 1) ? g_xl : g_wl;
#pragma unroll
    for (int i = 0; i < n4; i++) {
        float f[4] = {v[i].x * inv, v[i].y * inv, v[i].z * inv, v[i].w * inv};
        ushort4 wh, wl;
        unsigned short* ph = &wh.x;
        unsigned short* pl = &wl.x;
#pragma unroll
        for (int j = 0; j < 4; j++) {
            __nv_bfloat16 h = __float2bfloat16(f[j]);
            __nv_bfloat16 l = __float2bfloat16(f[j] - __bfloat162float(h));
            ph[j] = __bfloat16_as_ushort(h);
            pl[j] = __bfloat16_as_ushort(l);
        }
        size_t off = (size_t)warp * cols + (size_t)(lane + 32 * i) * 4;
        *(ushort4*)(dh + off) = wh;
        *(ushort4*)(dl + off) = wl;
    }
}

// ---------------- column means of x (two-phase, deterministic) -------------
__global__ void mean_partial_kernel(const float* __restrict__ x) {
    int d = blockIdx.x * 256 + threadIdx.x;
    int seg = blockIdx.y, b = blockIdx.z;
    const int L = SS / SEGS;
    const float* p = x + ((size_t)b * SS + (size_t)seg * L) * DD + d;
    float s = 0.f;
#pragma unroll 4
    for (int t = 0; t < L; t++) s += p[(size_t)t * DD];
    g_xm_part[(b * SEGS + seg) * DD + d] = s;
}

__global__ void mean_reduce_kernel() {
    int i = blockIdx.x * 256 + threadIdx.x;
    float s = 0.f;
#pragma unroll
    for (int seg = 0; seg < SEGS; seg++)
        s += g_xm_part[((i >> 10) * SEGS + seg) * DD + (i & (DD - 1))];
    g_xm[i] = s * (1.0f / (float)SS);
}

// ---------------- gate / retention (one warp per (b,r)) --------------------
__global__ void gate_ret_kernel(const float* __restrict__ gate_w,
                                const float* __restrict__ gate_bias,
                                const float* __restrict__ ret_w,
                                const float* __restrict__ ret_bias) {
    int warp = (blockIdx.x * blockDim.x + threadIdx.x) >> 5;
    int lane = threadIdx.x & 31;
    if (warp >= BB * RR) return;
    int b = warp >> 8, r = warp & (RR - 1);
    const float* xm = g_xm + (size_t)b * DD;
    const float* gw = gate_w + (size_t)r * DD;
    const float* rw = ret_w + (size_t)r * DD;
    float s1 = 0.f, s2 = 0.f;
#pragma unroll 8
    for (int i = lane; i < DD; i += 32) {
        float xv = xm[i];
        s1 = fmaf(xv, gw[i], s1);
        s2 = fmaf(xv, rw[i], s2);
    }
#pragma unroll
    for (int o = 16; o > 0; o >>= 1) {
        s1 += __shfl_xor_sync(0xFFFFFFFFu, s1, o);
        s2 += __shfl_xor_sync(0xFFFFFFFFu, s2, o);
    }
    if (lane == 0) {
        float gs = 1.0f / (1.0f + expf(-(s1 + gate_bias[r])));
        g_gate[warp] = (gs >= 0.001f) ? gs : 0.0f;
        g_ret[warp] = 1.0f / (1.0f + expf(-(s2 + ret_bias[r])));
    }
}

// ---------------- mma.sync bf16x3 GEMM: C[M,N] = A[M,K]*B[N,K]^T -----------
// 128x128 CTA tile, 16 warps (warp tile 32x32), K-chunks of 32, 2-stage
// cp.async double buffering, ONE __syncthreads per chunk.
// Grid: blockIdx.x = bn (fast), blockIdx.y = bm  => same-A CTAs co-scheduled.
#define TILE_B  8192               // one 128x32 bf16 tile, swizzled 64B rows
#define STAGE_B (4 * TILE_B)       // Ah, Al, Bh, Bl
#define SMEM_B  (2 * STAGE_B)      // 64 KB

__device__ __forceinline__ void stage_tile(const __nv_bfloat16* __restrict__ src,
                                           size_t row0, int K, int k0,
                                           uint32_t sbase, int tid) {
    int row = tid >> 2, u = tid & 3;          // 512 threads: one 16B each
    cp16(sbase + SWZ64(row * 64 + u * 16),
         src + (row0 + row) * (size_t)K + k0 + u * 8);
}

template <int MODE>
__global__ __launch_bounds__(512) void tc_gemm(float* __restrict__ Cout,
                                               int N, int K) {
    extern __shared__ char smem[];
    uint32_t sb = (uint32_t)__cvta_generic_to_shared(smem);
    int tid = threadIdx.x;
    int lane = tid & 31, wid = tid >> 5;
    int wm = wid >> 2, wn = wid & 3;          // warp tile rows wm*32, cols wn*32
    int bn = blockIdx.x, bm = blockIdx.y;     // TRANSPOSED grid (bn fast)

    const __nv_bfloat16* Ah = (MODE == 1) ? g_xh : g_ah;
    const __nv_bfloat16* Al = (MODE == 1) ? g_xl : g_al;
    const __nv_bfloat16* Bh = (MODE == 1) ? g_fh : g_wh;
    const __nv_bfloat16* Bl = (MODE == 1) ? g_fl : g_wl;

    size_t aRow0 = (size_t)bm * 128, bRow0 = (size_t)bn * 128;

    float acc[2][4][4];
#pragma unroll
    for (int i = 0; i < 2; i++)
#pragma unroll
        for (int j = 0; j < 4; j++)
#pragma unroll
            for (int q = 0; q < 4; q++) acc[i][j][q] = 0.f;

    const int nch = K / 32;
    // prologue: stage chunk 0
    stage_tile(Ah, aRow0, K, 0, sb + 0 * TILE_B, tid);
    stage_tile(Al, aRow0, K, 0, sb + 1 * TILE_B, tid);
    stage_tile(Bh, bRow0, K, 0, sb + 2 * TILE_B, tid);
    stage_tile(Bl, bRow0, K, 0, sb + 3 * TILE_B, tid);
    CP_COMMIT();
    CP_WAIT(0);
    __syncthreads();

    // ldmatrix lane offsets
    int aoff0 = (lane & 15) * 64 + (lane >> 4) * 16;
    int grp = lane >> 3, wtn = lane & 7;
    int boff0 = ((grp >> 1) * 8 + wtn) * 64 + (grp & 1) * 16;

    for (int c = 0; c < nch; c++) {
        // issue loads for c+1 (safe: target buffer's readers finished before
        // the barrier that ended iteration c-1)
        if (c + 1 < nch) {
            uint32_t st = sb + ((c + 1) & 1) * STAGE_B;
            int k0 = (c + 1) * 32;
            stage_tile(Ah, aRow0, K, k0, st + 0 * TILE_B, tid);
            stage_tile(Al, aRow0, K, k0, st + 1 * TILE_B, tid);
            stage_tile(Bh, bRow0, K, k0, st + 2 * TILE_B, tid);
            stage_tile(Bl, bRow0, K, k0, st + 3 * TILE_B, tid);
            CP_COMMIT();
        }

        uint32_t st = sb + (c & 1) * STAGE_B;
        uint32_t sAh = st, sAl = st + TILE_B, sBh = st + 2 * TILE_B, sBl = st + 3 * TILE_B;
#pragma unroll
        for (int ks = 0; ks < 2; ks++) {
            uint32_t af_h[2][4], af_l[2][4];
#pragma unroll
            for (int i = 0; i < 2; i++) {
                int off = SWZ64((wm * 32 + i * 16) * 64 + aoff0 + ks * 32);
                ldsm_x4(af_h[i], sAh + off);
                ldsm_x4(af_l[i], sAl + off);
            }
            uint32_t bf_h[2][4], bf_l[2][4];
#pragma unroll
            for (int h = 0; h < 2; h++) {
                int off = SWZ64((wn * 32 + h * 16) * 64 + boff0 + ks * 32);
                ldsm_x4(bf_h[h], sBh + off);
                ldsm_x4(bf_l[h], sBl + off);
            }
#pragma unroll
            for (int i = 0; i < 2; i++)
#pragma unroll
                for (int j = 0; j < 4; j++) {
                    int h = j >> 1, q = (j & 1) * 2;
                    mma_bf16(acc[i][j], af_h[i], bf_h[h][q], bf_h[h][q + 1]);
                    mma_bf16(acc[i][j], af_h[i], bf_l[h][q], bf_l[h][q + 1]);
                    mma_bf16(acc[i][j], af_l[i], bf_h[h][q], bf_h[h][q + 1]);
                }
        }
        if (c + 1 < nch) CP_WAIT(0);
        __syncthreads();
    }

    float* C = (MODE == 1) ? g_signal : Cout;
#pragma unroll
    for (int i = 0; i < 2; i++) {
        int m0 = bm * 128 + wm * 32 + i * 16 + (lane >> 2);
#pragma unroll
        for (int j = 0; j < 4; j++) {
            int n0 = bn * 128 + wn * 32 + j * 8 + (lane & 3) * 2;
            *(float2*)(C + (size_t)m0 * N + n0) = make_float2(acc[i][j][0], acc[i][j][1]);
            *(float2*)(C + (size_t)(m0 + 8) * N + n0) = make_float2(acc[i][j][2], acc[i][j][3]);
        }
    }
}

// ---------------- scan: acc_t = gate*sig_t + acc_{t-1}*retention -----------
__global__ void scan_kernel(const float* __restrict__ prev_state,
                            float* __restrict__ final_state_out) {
    int c = blockIdx.x * blockDim.x + threadIdx.x;  // 0..2047
    if (c >= BB * RR) return;
    int b = c >> 8, r = c & (RR - 1);
    float st = prev_state[c];
    float ret = g_ret[c];
    float gate = g_gate[c];
    size_t base = (size_t)b * SS * RR + r;
#pragma unroll 16
    for (int t = 0; t < SS; t++) {
        size_t pos = base + (size_t)t * RR;
        float v = g_signal[pos] * gate;
        st = fmaf(st, ret, v);
        __nv_bfloat16 h = __float2bfloat16(st);
        g_ah[pos] = h;
        g_al[pos] = __float2bfloat16(st - __bfloat162float(h));
    }
    if (final_state_out) final_state_out[c] = st;
}

// ---------------------------------------------------------------------------
extern "C" void kernel_launch(void* const* d_in, const int* in_sizes, int n_in,
                              void* d_out, int out_size) {
    const float* x         = (const float*)d_in[0];
    const float* prev_st   = (const float*)d_in[1];
    const float* freq      = (const float*)d_in[2];
    const float* ret_bias  = (const float*)d_in[3];
    const float* ret_w     = (const float*)d_in[4];
    const float* gate_w    = (const float*)d_in[5];
    const float* gate_bias = (const float*)d_in[6];
    const float* out_w     = (const float*)d_in[7];
    float* out = (float*)d_out;

    cudaFuncSetAttribute(tc_gemm<1>, cudaFuncAttributeMaxDynamicSharedMemorySize, SMEM_B);
    cudaFuncSetAttribute(tc_gemm<2>, cudaFuncAttributeMaxDynamicSharedMemorySize, SMEM_B);

    conv_kernel<0><<<RR / 8, 256>>>(freq, RR);                                   // 1
    conv_kernel<1><<<MTOT / 8, 256>>>(x, MTOT);                                  // 2
    mean_partial_kernel<<<dim3(DD / 256, SEGS, BB), 256>>>(x);                   // 3
    // 4) GEMM1 — my 4th launch = ncu's captured launch; grid (bn, bm)
    tc_gemm<1><<<dim3(RR / 128, MTOT / 128), 512, SMEM_B>>>(nullptr, RR, DD);    // 4
    mean_reduce_kernel<<<(BB * DD) / 256, 256>>>();                              // 5
    gate_ret_kernel<<<(BB * RR) / 8, 256>>>(gate_w, gate_bias, ret_w, ret_bias); // 6
    long long need_fs = (long long)MTOT * DD + BB * RR;
    float* fs_ptr = ((long long)out_size >= need_fs) ? (out + (size_t)MTOT * DD) : nullptr;
    scan_kernel<<<64, 32>>>(prev_st, fs_ptr);                                    // 7
    conv_kernel<2><<<DD / 8, 256>>>(out_w, DD);                                  // 8
    tc_gemm<2><<<dim3(DD / 128, MTOT / 128), 512, SMEM_B>>>(out, DD, RR);        // 9
}